// round 1
// baseline (speedup 1.0000x reference)
#include <cuda_runtime.h>
#include <cuda_bf16.h>

// ---------------------------------------------------------------------------
// FocDecoderRNN — fp32 baseline, structured for later tensor-core upgrade.
//
// Pipeline:
//   x1  = x(B,4096) @ embed1_w^T + b            (SGEMM-NT, K=4096)
//   gi1 = x1 @ w_ih1^T + b ; gh1 = h @ w_hh1^T + b
//   h1  = GRU(gi1, gh1, h)          -> written to out[y_h slot 0]
//   o1  = h1 @ out1_w^T + b ; y[b,i,:] = o1[b,i] (broadcast)
//   cells (cx,cy) from focal_area (row-major argwhere order)
//   gh2 = h @ w_hh2^T + b           (shared across all K cells)
//   patch[k] gathered from x ; e2[k] = patch @ embed2_w^T + b
//   gi2[k] = e2[k] @ w_ih2^T + b    (dominant GEMM, 26 GF)
//   h2[k] = GRU(gi2[k], gh2, h)     -> out[y_h slot 1+k]
//   o2[k] = h2[k] @ out2_w^T + b    -> scatter-ADD into y (fused epilogue)
//
// K (#cells) derived on HOST from out_size => grids fixed, graph-capturable.
// ---------------------------------------------------------------------------

#define BSZ   2048
#define HDIM  256
#define MAXK  64

// Scratch (static device globals; no runtime allocation).
__device__ float d_x1 [BSZ * 256];
__device__ float d_gi1[BSZ * 768];
__device__ float d_gh1[BSZ * 768];
__device__ float d_gh2[BSZ * 768];
__device__ float d_o1 [BSZ * 64];
__device__ float d_patch[(size_t)MAXK * BSZ * 64];
__device__ float d_e2   [(size_t)MAXK * BSZ * 256];
__device__ float d_gi2  [(size_t)MAXK * BSZ * 768];
__device__ int   d_cx[MAXK];
__device__ int   d_cy[MAXK];

// ---------------------------------------------------------------------------
// cells = argwhere(focal_area > 0.5) in row-major order
__global__ void find_cells_kernel(const float* __restrict__ fa,
                                  int* __restrict__ cx, int* __restrict__ cy)
{
    if (threadIdx.x == 0 && blockIdx.x == 0) {
        int k = 0;
        for (int i = 0; i < 8; i++)
            for (int j = 0; j < 8; j++)
                if (fa[i * 8 + j] > 0.5f) { cx[k] = i; cy[k] = j; k++; }
    }
}

// ---------------------------------------------------------------------------
// Generic SGEMM:  C[z][m,n] = sum_k A[z][m,k] * Bw[n,k] + bias[n]
// A row-major MxK (z-strided), Bw row-major NxK (shared), C row-major MxN.
// Requires: M%64==0, N%64==0, K%16==0, all pointers 16B aligned, K%4==0.
#define TBM 64
#define TBN 64
#define TBK 16

__global__ __launch_bounds__(256)
void sgemm_nt(const float* __restrict__ A, const float* __restrict__ Bw,
              const float* __restrict__ bias, float* __restrict__ C,
              int M, int N, int K, long long sAz, long long sCz)
{
    __shared__ float As[TBK][TBM + 4];   // row = k, col = m ; row stride 68 floats (16B aligned)
    __shared__ float Bs[TBK][TBN + 4];

    const int bm = blockIdx.y * TBM;
    const int bn = blockIdx.x * TBN;
    A += (long long)blockIdx.z * sAz;
    C += (long long)blockIdx.z * sCz;

    const int tid = threadIdx.x;
    const int tx  = tid & 15;       // 0..15 -> n
    const int ty  = tid >> 4;       // 0..15 -> m
    const int lr  = tid >> 2;       // 0..63  load row
    const int lc  = (tid & 3) * 4;  // 0,4,8,12 load k offset

    float acc[4][4];
#pragma unroll
    for (int i = 0; i < 4; i++)
#pragma unroll
        for (int j = 0; j < 4; j++) acc[i][j] = 0.f;

    for (int k0 = 0; k0 < K; k0 += TBK) {
        const float4 a4 = *reinterpret_cast<const float4*>(&A [(long long)(bm + lr) * K + k0 + lc]);
        const float4 b4 = *reinterpret_cast<const float4*>(&Bw[(long long)(bn + lr) * K + k0 + lc]);
        As[lc + 0][lr] = a4.x; As[lc + 1][lr] = a4.y; As[lc + 2][lr] = a4.z; As[lc + 3][lr] = a4.w;
        Bs[lc + 0][lr] = b4.x; Bs[lc + 1][lr] = b4.y; Bs[lc + 2][lr] = b4.z; Bs[lc + 3][lr] = b4.w;
        __syncthreads();
#pragma unroll
        for (int kk = 0; kk < TBK; kk++) {
            const float4 av = *reinterpret_cast<const float4*>(&As[kk][ty * 4]);
            const float4 bv = *reinterpret_cast<const float4*>(&Bs[kk][tx * 4]);
            const float a[4] = {av.x, av.y, av.z, av.w};
            const float b[4] = {bv.x, bv.y, bv.z, bv.w};
#pragma unroll
            for (int i = 0; i < 4; i++)
#pragma unroll
                for (int j = 0; j < 4; j++) acc[i][j] += a[i] * b[j];
        }
        __syncthreads();
    }

#pragma unroll
    for (int i = 0; i < 4; i++) {
        const int row = bm + ty * 4 + i;
#pragma unroll
        for (int j = 0; j < 4; j++) {
            const int col = bn + tx * 4 + j;
            C[(long long)row * N + col] = acc[i][j] + bias[col];
        }
    }
}

// ---------------------------------------------------------------------------
// o2 GEMM with fused scatter-ADD into y. N=64 (one tile). z = cell index.
// y[b*4096 + cx*512 + (n/8)*64 + cy*8 + (n%8)] += acc + bias[n]
__global__ __launch_bounds__(256)
void sgemm_nt_scatter(const float* __restrict__ A, const float* __restrict__ Bw,
                      const float* __restrict__ bias, float* __restrict__ y,
                      const int* __restrict__ cxs, const int* __restrict__ cys,
                      int K, long long sAz)
{
    __shared__ float As[TBK][TBM + 4];
    __shared__ float Bs[TBK][TBN + 4];

    const int bm = blockIdx.y * TBM;
    A += (long long)blockIdx.z * sAz;
    const int cellx = cxs[blockIdx.z];
    const int celly = cys[blockIdx.z];

    const int tid = threadIdx.x;
    const int tx  = tid & 15;
    const int ty  = tid >> 4;
    const int lr  = tid >> 2;
    const int lc  = (tid & 3) * 4;

    float acc[4][4];
#pragma unroll
    for (int i = 0; i < 4; i++)
#pragma unroll
        for (int j = 0; j < 4; j++) acc[i][j] = 0.f;

    for (int k0 = 0; k0 < K; k0 += TBK) {
        const float4 a4 = *reinterpret_cast<const float4*>(&A [(long long)(bm + lr) * K + k0 + lc]);
        const float4 b4 = *reinterpret_cast<const float4*>(&Bw[(long long)lr * K + k0 + lc]); // N=64 rows
        As[lc + 0][lr] = a4.x; As[lc + 1][lr] = a4.y; As[lc + 2][lr] = a4.z; As[lc + 3][lr] = a4.w;
        Bs[lc + 0][lr] = b4.x; Bs[lc + 1][lr] = b4.y; Bs[lc + 2][lr] = b4.z; Bs[lc + 3][lr] = b4.w;
        __syncthreads();
#pragma unroll
        for (int kk = 0; kk < TBK; kk++) {
            const float4 av = *reinterpret_cast<const float4*>(&As[kk][ty * 4]);
            const float4 bv = *reinterpret_cast<const float4*>(&Bs[kk][tx * 4]);
            const float a[4] = {av.x, av.y, av.z, av.w};
            const float b[4] = {bv.x, bv.y, bv.z, bv.w};
#pragma unroll
            for (int i = 0; i < 4; i++)
#pragma unroll
                for (int j = 0; j < 4; j++) acc[i][j] += a[i] * b[j];
        }
        __syncthreads();
    }

#pragma unroll
    for (int i = 0; i < 4; i++) {
        const int row = bm + ty * 4 + i;   // batch index b
#pragma unroll
        for (int j = 0; j < 4; j++) {
            const int col = tx * 4 + j;    // 0..63 = r*8+c
            const long long off = (long long)row * 4096 + cellx * 512
                                + (col >> 3) * 64 + celly * 8 + (col & 7);
            y[off] += acc[i][j] + bias[col];
        }
    }
}

// ---------------------------------------------------------------------------
// GRU elementwise.  z = cell (or 0). gh/h0 shared across z.
__global__ void gru_elem_kernel(const float* __restrict__ gi, const float* __restrict__ gh,
                                const float* __restrict__ h0, float* __restrict__ hout,
                                int n_per, long long giZ, long long hoZ)
{
    const long long z = blockIdx.z;
    const int idx = blockIdx.x * blockDim.x + threadIdx.x;   // over B*H
    if (idx >= n_per) return;
    const int b = idx >> 8;          // /H (H=256)
    const int j = idx & 255;
    const float* g  = gi + z * giZ + (long long)b * 768;
    const float* gg = gh + (long long)b * 768;
    const float ir = g[j],        iz = g[j + 256],  inn = g[j + 512];
    const float hr = gg[j],       hz = gg[j + 256], hn  = gg[j + 512];
    const float r  = 1.f / (1.f + expf(-(ir + hr)));
    const float zz = 1.f / (1.f + expf(-(iz + hz)));
    const float n  = tanhf(inn + r * hn);
    hout[z * hoZ + idx] = (1.f - zz) * n + zz * h0[idx];
}

// ---------------------------------------------------------------------------
// y[b, i, :] = o1[b, i]  (broadcast over last 64)
__global__ void bcast_y_kernel(const float* __restrict__ o1, float* __restrict__ y, int total)
{
    const int idx = blockIdx.x * blockDim.x + threadIdx.x;   // over B*64
    if (idx >= total) return;
    const float v = o1[idx];
    float4 v4 = make_float4(v, v, v, v);
    float4* p = reinterpret_cast<float4*>(y + (long long)idx * 64);
#pragma unroll
    for (int j = 0; j < 16; j++) p[j] = v4;
}

// ---------------------------------------------------------------------------
// patch[z, b, t] = x[b, cx*512 + (t/8)*64 + cy*8 + t%8]
__global__ void gather_patches_kernel(const float* __restrict__ x,
                                      const int* __restrict__ cxs, const int* __restrict__ cys,
                                      float* __restrict__ P, int n_per)
{
    const int z = blockIdx.z;
    const int idx = blockIdx.x * blockDim.x + threadIdx.x;   // over B*64
    if (idx >= n_per) return;
    const int b = idx >> 6, t = idx & 63;
    const int cellx = cxs[z], celly = cys[z];
    P[(long long)z * n_per + idx] =
        x[(long long)b * 4096 + cellx * 512 + (t >> 3) * 64 + celly * 8 + (t & 7)];
}

// ---------------------------------------------------------------------------
extern "C" void kernel_launch(void* const* d_in, const int* in_sizes, int n_in,
                              void* d_out, int out_size)
{
    const float* x    = (const float*)d_in[0];
    const float* h    = (const float*)d_in[1];   // (1,B,H) -> contiguous B x H
    const float* fa   = (const float*)d_in[2];
    const float* e1w  = (const float*)d_in[3];
    const float* e1b  = (const float*)d_in[4];
    const float* wih1 = (const float*)d_in[5];
    const float* whh1 = (const float*)d_in[6];
    const float* bih1 = (const float*)d_in[7];
    const float* bhh1 = (const float*)d_in[8];
    const float* o1w  = (const float*)d_in[9];
    const float* o1b  = (const float*)d_in[10];
    const float* e2w  = (const float*)d_in[11];
    const float* e2b  = (const float*)d_in[12];
    const float* wih2 = (const float*)d_in[13];
    const float* whh2 = (const float*)d_in[14];
    const float* bih2 = (const float*)d_in[15];
    const float* bhh2 = (const float*)d_in[16];
    const float* o2w  = (const float*)d_in[17];
    const float* o2b  = (const float*)d_in[18];
    float* out = (float*)d_out;

    const int B = in_sizes[0] / 4096;                    // 2048
    const long long YOFF = (long long)B * 4096;          // y elements
    int Kc = (int)(((long long)out_size - YOFF) / ((long long)B * HDIM)) - 1;
    if (Kc < 0) Kc = 0;
    if (Kc > MAXK) Kc = MAXK;

    // resolve scratch symbols (query only; no allocation)
    float *p_x1, *p_gi1, *p_gh1, *p_gh2, *p_o1, *p_patch, *p_e2, *p_gi2;
    int   *p_cx, *p_cy;
    cudaGetSymbolAddress((void**)&p_x1,    d_x1);
    cudaGetSymbolAddress((void**)&p_gi1,   d_gi1);
    cudaGetSymbolAddress((void**)&p_gh1,   d_gh1);
    cudaGetSymbolAddress((void**)&p_gh2,   d_gh2);
    cudaGetSymbolAddress((void**)&p_o1,    d_o1);
    cudaGetSymbolAddress((void**)&p_patch, d_patch);
    cudaGetSymbolAddress((void**)&p_e2,    d_e2);
    cudaGetSymbolAddress((void**)&p_gi2,   d_gi2);
    cudaGetSymbolAddress((void**)&p_cx,    d_cx);
    cudaGetSymbolAddress((void**)&p_cy,    d_cy);

    float* yh0 = out + YOFF;                 // h1 slot
    float* yh2 = out + YOFF + (long long)B * HDIM;  // h2 slots (K of them)

    find_cells_kernel<<<1, 32>>>(fa, p_cx, p_cy);

    // x1 = x @ e1w^T + e1b        (M=B, N=256, K=4096)
    sgemm_nt<<<dim3(256 / TBN, B / TBM), 256>>>(x, e1w, e1b, p_x1, B, 256, 4096, 0, 0);
    // gi1 = x1 @ wih1^T + b       (N=768, K=256)
    sgemm_nt<<<dim3(768 / TBN, B / TBM), 256>>>(p_x1, wih1, bih1, p_gi1, B, 768, 256, 0, 0);
    // gh1 = h  @ whh1^T + b
    sgemm_nt<<<dim3(768 / TBN, B / TBM), 256>>>(h, whh1, bhh1, p_gh1, B, 768, 256, 0, 0);
    // h1 -> out y_h[0]
    gru_elem_kernel<<<dim3((B * HDIM + 255) / 256, 1, 1), 256>>>(p_gi1, p_gh1, h, yh0, B * HDIM, 0, 0);
    // o1 = h1 @ o1w^T + b         (N=64, K=256)
    sgemm_nt<<<dim3(1, B / TBM), 256>>>(yh0, o1w, o1b, p_o1, B, 64, 256, 0, 0);
    // broadcast y
    bcast_y_kernel<<<(B * 64 + 255) / 256, 256>>>(p_o1, out, B * 64);

    if (Kc > 0) {
        // gh2 shared across cells
        sgemm_nt<<<dim3(768 / TBN, B / TBM), 256>>>(h, whh2, bhh2, p_gh2, B, 768, 256, 0, 0);
        // gather patches
        gather_patches_kernel<<<dim3((B * 64 + 255) / 256, 1, Kc), 256>>>(x, p_cx, p_cy, p_patch, B * 64);
        // e2[k] = patch[k] @ e2w^T + b   (N=256, K=64)
        sgemm_nt<<<dim3(256 / TBN, B / TBM, Kc), 256>>>(p_patch, e2w, e2b, p_e2,
                                                        B, 256, 64,
                                                        (long long)B * 64, (long long)B * 256);
        // gi2[k] = e2[k] @ wih2^T + b    (dominant GEMM: N=768, K=256, z=Kc)
        sgemm_nt<<<dim3(768 / TBN, B / TBM, Kc), 256>>>(p_e2, wih2, bih2, p_gi2,
                                                        B, 768, 256,
                                                        (long long)B * 256, (long long)B * 768);
        // h2[k] -> out y_h[1+k]
        gru_elem_kernel<<<dim3((B * HDIM + 255) / 256, 1, Kc), 256>>>(p_gi2, p_gh2, h, yh2,
                                                                      B * HDIM,
                                                                      (long long)B * 768,
                                                                      (long long)B * HDIM);
        // o2[k] = h2[k] @ o2w^T + b, scatter-ADD into y (distinct cells => race-free)
        sgemm_nt_scatter<<<dim3(1, B / TBM, Kc), 256>>>(yh2, o2w, o2b, out, p_cx, p_cy,
                                                        256, (long long)B * HDIM);
    }
}

// round 2
// speedup vs baseline: 2.0629x; 2.0629x over previous
#include <cuda_runtime.h>
#include <cstdint>

// ---------------------------------------------------------------------------
// FocDecoderRNN — TF32 tensor-core version with algebraic fusion.
//
//   gi2 = e2 @ w_ih2^T   where e2 = patch @ e2w^T + e2b
//       = patch @ (w_ih2 @ e2w)^T + (b_ih2 + w_ih2 @ e2b)   <- K: 256 -> 64
//   e2 / patch buffers eliminated; gather fused into GEMM A load.
//   All GEMMs use mma.sync m16n8k8 tf32. Epilogues fuse bias, y-broadcast
//   (o1) and y-scatter-add (o2).
// ---------------------------------------------------------------------------

#define BSZ   2048
#define HDIM  256
#define MAXK  64

__device__ float d_x1 [BSZ * 256];
__device__ float d_gi1[BSZ * 768];
__device__ float d_gh1[BSZ * 768];
__device__ float d_gh2[BSZ * 768];
__device__ float d_gi2[(size_t)MAXK * BSZ * 768];
__device__ float d_w2p[768 * 64];
__device__ float d_b2p[768];
__device__ int   d_cx[MAXK];
__device__ int   d_cy[MAXK];

// ---------------------------------------------------------------------------
__global__ void find_cells_kernel(const float* __restrict__ fa,
                                  int* __restrict__ cx, int* __restrict__ cy)
{
    if (threadIdx.x == 0 && blockIdx.x == 0) {
        int k = 0;
        for (int i = 0; i < 8; i++)
            for (int j = 0; j < 8; j++)
                if (fa[i * 8 + j] > 0.5f) { cx[k] = i; cy[k] = j; k++; }
    }
}

// W2p[n][t] = sum_c wih2[n][c] * e2w[c][t] ;  b2p[n] = bih2[n] + dot(wih2[n], e2b)
__global__ void compose_w2_kernel(const float* __restrict__ wih2,
                                  const float* __restrict__ e2w,
                                  const float* __restrict__ e2b,
                                  const float* __restrict__ bih2,
                                  float* __restrict__ W2p, float* __restrict__ b2p)
{
    const int n = blockIdx.x;      // 0..767
    const int t = threadIdx.x;     // 0..63
    float s = 0.f;
    for (int c = 0; c < 256; c++)
        s += wih2[n * 256 + c] * e2w[c * 64 + t];
    W2p[n * 64 + t] = s;
    if (t == 0) {
        float sb = 0.f;
        for (int c = 0; c < 256; c++) sb += wih2[n * 256 + c] * e2b[c];
        b2p[n] = bih2[n] + sb;
    }
}

// ---------------------------------------------------------------------------
__device__ __forceinline__ uint32_t f2tf32(float x)
{
    uint32_t u;
    asm("cvt.rna.tf32.f32 %0, %1;" : "=r"(u) : "f"(x));
    return u;
}

__device__ __forceinline__ void mma_tf32(float c[4], const uint32_t a[4], const uint32_t b[2])
{
    asm volatile(
        "mma.sync.aligned.m16n8k8.row.col.f32.tf32.tf32.f32 "
        "{%0,%1,%2,%3},{%4,%5,%6,%7},{%8,%9},{%0,%1,%2,%3};\n"
        : "+f"(c[0]), "+f"(c[1]), "+f"(c[2]), "+f"(c[3])
        : "r"(a[0]), "r"(a[1]), "r"(a[2]), "r"(a[3]), "r"(b[0]), "r"(b[1]));
}

// ---------------------------------------------------------------------------
// TF32 GEMM-NT:  C[z](M,N) = A[z](M,K) @ Bw(N,K)^T + bias
//   AMODE 0: A normal (z-strided).  AMODE 1: A = patch gather from x (K==64).
//   EMODE 0: store.  EMODE 1: scatter-add into y.  EMODE 2: broadcast into y.
// Block 256 thr, tile 128x64xK16; 8 warps of 32x32; mma m16n8k8 tf32.
// Requires M%128==0, N%64==0, K%16==0.
template<int AMODE, int EMODE>
__global__ __launch_bounds__(256)
void gemm_tf32(const float* __restrict__ A, const float* __restrict__ Bw,
               const float* __restrict__ bias, float* __restrict__ C,
               int M, int N, int K, long long sAz, long long sCz,
               const int* __restrict__ cxs, const int* __restrict__ cys)
{
    __shared__ uint32_t As[128][20];   // [m][k], pad 4 -> conflict-free frag loads
    __shared__ uint32_t Bs[64][20];    // [n][k]

    const int bm = blockIdx.y * 128;
    const int bn = blockIdx.x * 64;
    int cellx = 0, celly = 0;
    if (AMODE == 1 || EMODE == 1) { cellx = cxs[blockIdx.z]; celly = cys[blockIdx.z]; }
    if (AMODE == 0) A += (long long)blockIdx.z * sAz;
    if (EMODE == 0) C += (long long)blockIdx.z * sCz;

    const int tid  = threadIdx.x;
    const int lane = tid & 31;
    const int wid  = tid >> 5;
    const int wm   = wid & 3;          // 0..3  -> m offset wm*32
    const int wn   = wid >> 2;         // 0..1  -> n offset wn*32
    const int g    = lane >> 2;        // 0..7
    const int t    = lane & 3;         // 0..3
    const int ar   = tid >> 1;         // 0..127 A load row
    const int ac   = (tid & 1) * 8;    // 0 or 8 A load col
    const int br   = tid >> 2;         // 0..63  B load row
    const int bc   = (tid & 3) * 4;    // 0..12  B load col

    float acc[2][4][4];
#pragma unroll
    for (int i = 0; i < 2; i++)
#pragma unroll
        for (int j = 0; j < 4; j++)
#pragma unroll
            for (int q = 0; q < 4; q++) acc[i][j][q] = 0.f;

    for (int k0 = 0; k0 < K; k0 += 16) {
        // ---- A tile load (8 floats/thread) ----
        const float* ap;
        if (AMODE == 0) {
            ap = A + (long long)(bm + ar) * K + k0 + ac;
        } else {
            const int tt = k0 + ac;          // multiple of 8
            ap = A + (long long)(bm + ar) * 4096 + cellx * 512 + (tt >> 3) * 64 + celly * 8;
        }
        const float4 av0 = *reinterpret_cast<const float4*>(ap);
        const float4 av1 = *reinterpret_cast<const float4*>(ap + 4);
        As[ar][ac + 0] = f2tf32(av0.x); As[ar][ac + 1] = f2tf32(av0.y);
        As[ar][ac + 2] = f2tf32(av0.z); As[ar][ac + 3] = f2tf32(av0.w);
        As[ar][ac + 4] = f2tf32(av1.x); As[ar][ac + 5] = f2tf32(av1.y);
        As[ar][ac + 6] = f2tf32(av1.z); As[ar][ac + 7] = f2tf32(av1.w);
        // ---- B tile load (4 floats/thread) ----
        const float4 bv = *reinterpret_cast<const float4*>(Bw + (long long)(bn + br) * K + k0 + bc);
        Bs[br][bc + 0] = f2tf32(bv.x); Bs[br][bc + 1] = f2tf32(bv.y);
        Bs[br][bc + 2] = f2tf32(bv.z); Bs[br][bc + 3] = f2tf32(bv.w);
        __syncthreads();

#pragma unroll
        for (int kk = 0; kk < 16; kk += 8) {
            uint32_t af[2][4], bf[4][2];
#pragma unroll
            for (int i = 0; i < 2; i++) {
                const int m = wm * 32 + i * 16;
                af[i][0] = As[m + g][kk + t];
                af[i][1] = As[m + 8 + g][kk + t];
                af[i][2] = As[m + g][kk + t + 4];
                af[i][3] = As[m + 8 + g][kk + t + 4];
            }
#pragma unroll
            for (int j = 0; j < 4; j++) {
                const int n = wn * 32 + j * 8;
                bf[j][0] = Bs[n + g][kk + t];
                bf[j][1] = Bs[n + g][kk + t + 4];
            }
#pragma unroll
            for (int i = 0; i < 2; i++)
#pragma unroll
                for (int j = 0; j < 4; j++) mma_tf32(acc[i][j], af[i], bf[j]);
        }
        __syncthreads();
    }

    // ---- epilogue ----
#pragma unroll
    for (int i = 0; i < 2; i++) {
        const int row0 = bm + wm * 32 + i * 16 + g;
#pragma unroll
        for (int j = 0; j < 4; j++) {
            const int col = bn + wn * 32 + j * 8 + 2 * t;
            const float bz0 = __ldg(&bias[col]);
            const float bz1 = __ldg(&bias[col + 1]);
            const float v0 = acc[i][j][0] + bz0, v1 = acc[i][j][1] + bz1;
            const float v2 = acc[i][j][2] + bz0, v3 = acc[i][j][3] + bz1;
            if (EMODE == 0) {
                *reinterpret_cast<float2*>(&C[(long long)row0 * N + col])       = make_float2(v0, v1);
                *reinterpret_cast<float2*>(&C[(long long)(row0 + 8) * N + col]) = make_float2(v2, v3);
            } else if (EMODE == 1) {
                // scatter-add into y: col (0..63) = r*8+c of the SxS patch
                const long long off0 = (long long)row0 * 4096 + cellx * 512
                                     + (col >> 3) * 64 + celly * 8 + (col & 7);
                C[off0]     += v0;  C[off0 + 1] += v1;
                const long long off2 = off0 + 8LL * 4096;
                C[off2]     += v2;  C[off2 + 1] += v3;
            } else {
                // broadcast: y[row, col, 0..63] = v
                float4* p0 = reinterpret_cast<float4*>(C + (long long)row0 * 4096 + (long long)col * 64);
                float4* p2 = reinterpret_cast<float4*>(C + (long long)(row0 + 8) * 4096 + (long long)col * 64);
                const float4 f0 = make_float4(v0, v0, v0, v0);
                const float4 f1 = make_float4(v1, v1, v1, v1);
                const float4 f2 = make_float4(v2, v2, v2, v2);
                const float4 f3 = make_float4(v3, v3, v3, v3);
#pragma unroll
                for (int q = 0; q < 16; q++) {
                    p0[q] = f0; p0[q + 16] = f1;
                    p2[q] = f2; p2[q + 16] = f3;
                }
            }
        }
    }
}

// ---------------------------------------------------------------------------
__global__ void gru_elem_kernel(const float* __restrict__ gi, const float* __restrict__ gh,
                                const float* __restrict__ h0, float* __restrict__ hout,
                                int n_per, long long giZ, long long hoZ)
{
    const long long z = blockIdx.z;
    const int idx = blockIdx.x * blockDim.x + threadIdx.x;   // over B*H
    if (idx >= n_per) return;
    const int b = idx >> 8;
    const int j = idx & 255;
    const float* gg = gh + (long long)b * 768;
    const float* g  = gi + z * giZ + (long long)b * 768;
    const float ir = g[j],  iz = g[j + 256],  inn = g[j + 512];
    const float hr = gg[j], hz = gg[j + 256], hn  = gg[j + 512];
    const float r  = 1.f / (1.f + expf(-(ir + hr)));
    const float zz = 1.f / (1.f + expf(-(iz + hz)));
    const float n  = tanhf(inn + r * hn);
    hout[z * hoZ + idx] = (1.f - zz) * n + zz * h0[idx];
}

// ---------------------------------------------------------------------------
extern "C" void kernel_launch(void* const* d_in, const int* in_sizes, int n_in,
                              void* d_out, int out_size)
{
    const float* x    = (const float*)d_in[0];
    const float* h    = (const float*)d_in[1];
    const float* fa   = (const float*)d_in[2];
    const float* e1w  = (const float*)d_in[3];
    const float* e1b  = (const float*)d_in[4];
    const float* wih1 = (const float*)d_in[5];
    const float* whh1 = (const float*)d_in[6];
    const float* bih1 = (const float*)d_in[7];
    const float* bhh1 = (const float*)d_in[8];
    const float* o1w  = (const float*)d_in[9];
    const float* o1b  = (const float*)d_in[10];
    const float* e2w  = (const float*)d_in[11];
    const float* e2b  = (const float*)d_in[12];
    const float* wih2 = (const float*)d_in[13];
    const float* whh2 = (const float*)d_in[14];
    const float* bih2 = (const float*)d_in[15];
    const float* bhh2 = (const float*)d_in[16];
    const float* o2w  = (const float*)d_in[17];
    const float* o2b  = (const float*)d_in[18];
    float* out = (float*)d_out;

    const int B = in_sizes[0] / 4096;                    // 2048
    const long long YOFF = (long long)B * 4096;
    int Kc = (int)(((long long)out_size - YOFF) / ((long long)B * HDIM)) - 1;
    if (Kc < 0) Kc = 0;
    if (Kc > MAXK) Kc = MAXK;

    float *p_x1, *p_gi1, *p_gh1, *p_gh2, *p_gi2, *p_w2p, *p_b2p;
    int *p_cx, *p_cy;
    cudaGetSymbolAddress((void**)&p_x1,  d_x1);
    cudaGetSymbolAddress((void**)&p_gi1, d_gi1);
    cudaGetSymbolAddress((void**)&p_gh1, d_gh1);
    cudaGetSymbolAddress((void**)&p_gh2, d_gh2);
    cudaGetSymbolAddress((void**)&p_gi2, d_gi2);
    cudaGetSymbolAddress((void**)&p_w2p, d_w2p);
    cudaGetSymbolAddress((void**)&p_b2p, d_b2p);
    cudaGetSymbolAddress((void**)&p_cx,  d_cx);
    cudaGetSymbolAddress((void**)&p_cy,  d_cy);

    float* yh0 = out + YOFF;                            // h1 slot
    float* yh2 = out + YOFF + (long long)B * HDIM;      // h2 slots

    find_cells_kernel<<<1, 32>>>(fa, p_cx, p_cy);
    compose_w2_kernel<<<768, 64>>>(wih2, e2w, e2b, bih2, p_w2p, p_b2p);

    // x1 = x @ e1w^T + e1b                       (N=256, K=4096)
    gemm_tf32<0, 0><<<dim3(256 / 64, B / 128), 256>>>(x, e1w, e1b, p_x1,
                                                      B, 256, 4096, 0, 0, p_cx, p_cy);
    // gi1 = x1 @ wih1^T + b                      (N=768, K=256)
    gemm_tf32<0, 0><<<dim3(768 / 64, B / 128), 256>>>(p_x1, wih1, bih1, p_gi1,
                                                      B, 768, 256, 0, 0, p_cx, p_cy);
    // gh1 = h @ whh1^T + b
    gemm_tf32<0, 0><<<dim3(768 / 64, B / 128), 256>>>(h, whh1, bhh1, p_gh1,
                                                      B, 768, 256, 0, 0, p_cx, p_cy);
    // h1 -> out y_h[0]
    gru_elem_kernel<<<dim3((B * HDIM + 255) / 256, 1, 1), 256>>>(p_gi1, p_gh1, h, yh0,
                                                                 B * HDIM, 0, 0);
    // o1 = h1 @ o1w^T + b, fused broadcast into y  (N=64, K=256)
    gemm_tf32<0, 2><<<dim3(1, B / 128), 256>>>(yh0, o1w, o1b, out,
                                               B, 64, 256, 0, 0, p_cx, p_cy);

    if (Kc > 0) {
        // gh2 = h @ whh2^T + b (shared across cells)
        gemm_tf32<0, 0><<<dim3(768 / 64, B / 128), 256>>>(h, whh2, bhh2, p_gh2,
                                                          B, 768, 256, 0, 0, p_cx, p_cy);
        // gi2[k] = patch[k] @ W2p^T + b2p          (fused gather; N=768, K=64)
        gemm_tf32<1, 0><<<dim3(768 / 64, B / 128, Kc), 256>>>(x, p_w2p, p_b2p, p_gi2,
                                                              B, 768, 64, 0,
                                                              (long long)B * 768, p_cx, p_cy);
        // h2[k] -> out y_h[1+k]
        gru_elem_kernel<<<dim3((B * HDIM + 255) / 256, 1, Kc), 256>>>(p_gi2, p_gh2, h, yh2,
                                                                      B * HDIM,
                                                                      (long long)B * 768,
                                                                      (long long)B * HDIM);
        // o2[k] = h2[k] @ o2w^T + b, fused scatter-ADD into y  (N=64, K=256)
        gemm_tf32<0, 1><<<dim3(1, B / 128, Kc), 256>>>(yh2, o2w, o2b, out,
                                                       B, 64, 256,
                                                       (long long)B * HDIM, 0, p_cx, p_cy);
    }
}

// round 3
// speedup vs baseline: 3.7776x; 1.8312x over previous
#include <cuda_runtime.h>
#include <cstdint>

// ---------------------------------------------------------------------------
// FocDecoderRNN — TF32 tensor cores, double-buffered GEMM engine.
//   gi2 = patch @ (w_ih2 @ e2w)^T + (b_ih2 + w_ih2 @ e2b)    (K: 256 -> 64)
//   x1 via split-K=4 + deterministic reduce.
//   y built in one assemble pass: y = bcast(o1) + scatter(o2).
// ---------------------------------------------------------------------------

#define BSZ  2048
#define MAXK 64

__device__ float d_xp [4 * BSZ * 256];
__device__ float d_x1 [BSZ * 256];
__device__ float d_gi1[BSZ * 768];
__device__ float d_gh1[BSZ * 768];
__device__ float d_gh2[BSZ * 768];
__device__ float d_gi2[(size_t)MAXK * BSZ * 768];
__device__ float d_o1 [BSZ * 64];
__device__ float d_o2 [(size_t)MAXK * BSZ * 64];
__device__ float d_w2p[768 * 64];
__device__ float d_b2p[768];
__device__ int   d_cx[MAXK], d_cy[MAXK], d_cmap[64];

// ---------------------------------------------------------------------------
__global__ void find_cells_kernel(const float* __restrict__ fa,
                                  int* __restrict__ cx, int* __restrict__ cy,
                                  int* __restrict__ cmap)
{
    if (threadIdx.x == 0 && blockIdx.x == 0) {
        for (int i = 0; i < 64; i++) cmap[i] = -1;
        int k = 0;
        for (int i = 0; i < 8; i++)
            for (int j = 0; j < 8; j++)
                if (fa[i * 8 + j] > 0.5f) { cx[k] = i; cy[k] = j; cmap[i * 8 + j] = k; k++; }
    }
}

// W2p[n][t] = sum_c wih2[n][c] * e2w[c][t] ;  b2p[n] = bih2[n] + dot(wih2[n], e2b)
__global__ void compose_w2_kernel(const float* __restrict__ wih2,
                                  const float* __restrict__ e2w,
                                  const float* __restrict__ e2b,
                                  const float* __restrict__ bih2,
                                  float* __restrict__ W2p, float* __restrict__ b2p)
{
    const int n = blockIdx.x;      // 0..767
    const int t = threadIdx.x;     // 0..63
    float s = 0.f;
    for (int c = 0; c < 256; c++)
        s += wih2[n * 256 + c] * e2w[c * 64 + t];
    W2p[n * 64 + t] = s;
    if (t == 0) {
        float sb = 0.f;
        for (int c = 0; c < 256; c++) sb += wih2[n * 256 + c] * e2b[c];
        b2p[n] = bih2[n] + sb;
    }
}

// ---------------------------------------------------------------------------
__device__ __forceinline__ uint32_t f2tf32(float x)
{
    uint32_t u;
    asm("cvt.rna.tf32.f32 %0, %1;" : "=r"(u) : "f"(x));
    return u;
}

__device__ __forceinline__ void mma_tf32(float c[4], const uint32_t a[4], const uint32_t b[2])
{
    asm volatile(
        "mma.sync.aligned.m16n8k8.row.col.f32.tf32.tf32.f32 "
        "{%0,%1,%2,%3},{%4,%5,%6,%7},{%8,%9},{%0,%1,%2,%3};\n"
        : "+f"(c[0]), "+f"(c[1]), "+f"(c[2]), "+f"(c[3])
        : "r"(a[0]), "r"(a[1]), "r"(a[2]), "r"(a[3]), "r"(b[0]), "r"(b[1]));
}

// ---------------------------------------------------------------------------
// Double-buffered TF32 GEMM-NT:  C[z](M,N) = A[z](M,K) @ Bw[z](N,K)^T (+bias)
//   NT:    128 (8 warps as 2x4, warp 64x32) or 64 (4x2, warp 32x32)
//   AMODE: 0 = normal A (lda row stride), 1 = patch gather from x (K=64)
// Requires M%128==0, N%NT==0, K%16==0.
template<int NT, int AMODE>
__global__ __launch_bounds__(256)
void gemm_tc(const float* __restrict__ A, const float* __restrict__ Bw,
             const float* __restrict__ bias, float* __restrict__ C,
             int M, int N, int K, int lda, int ldb,
             long long sAz, long long sBz, long long sCz,
             const int* __restrict__ cxs, const int* __restrict__ cys)
{
    constexpr int WN  = (NT == 128) ? 4 : 2;   // warps along n
    constexpr int MF  = (NT == 128) ? 4 : 2;   // m fragments per warp
    constexpr int NF  = 4;                     // n fragments per warp
    constexpr int WMS = MF * 16;               // warp m span
    constexpr int BLD = (NT == 128) ? 8 : 4;   // B floats loaded per thread

    __shared__ uint32_t As[2][128][20];
    __shared__ uint32_t Bs[2][NT][20];

    const int bm = blockIdx.y * 128;
    const int bn = blockIdx.x * NT;
    int cellx = 0, celly = 0;
    if (AMODE == 1) { cellx = cxs[blockIdx.z]; celly = cys[blockIdx.z]; }
    if (AMODE == 0) A += (long long)blockIdx.z * sAz;
    Bw += (long long)blockIdx.z * sBz;
    C  += (long long)blockIdx.z * sCz;

    const int tid  = threadIdx.x;
    const int lane = tid & 31;
    const int wid  = tid >> 5;
    const int wm   = wid / WN;
    const int wn   = wid % WN;
    const int g    = lane >> 2;
    const int t    = lane & 3;
    const int ar   = tid >> 1;                 // 0..127
    const int ac   = (tid & 1) * 8;            // 0 / 8
    const int br   = (NT == 128) ? (tid >> 1) : (tid >> 2);
    const int bc   = (NT == 128) ? (tid & 1) * 8 : (tid & 3) * 4;

    float acc[MF][NF][4];
#pragma unroll
    for (int i = 0; i < MF; i++)
#pragma unroll
        for (int j = 0; j < NF; j++)
#pragma unroll
            for (int q = 0; q < 4; q++) acc[i][j][q] = 0.f;

    float a_pref[8], b_pref[BLD];

    // ---- prologue: load slab 0 ----
    {
        const float* ap;
        if (AMODE == 0) ap = A + (long long)(bm + ar) * lda + ac;
        else            ap = A + (long long)(bm + ar) * 4096 + cellx * 512 + ((ac >> 3) << 6) + celly * 8;
        const float4 v0 = *reinterpret_cast<const float4*>(ap);
        const float4 v1 = *reinterpret_cast<const float4*>(ap + 4);
        a_pref[0]=v0.x; a_pref[1]=v0.y; a_pref[2]=v0.z; a_pref[3]=v0.w;
        a_pref[4]=v1.x; a_pref[5]=v1.y; a_pref[6]=v1.z; a_pref[7]=v1.w;
        const float* bp = Bw + (long long)(bn + br) * ldb + bc;
        const float4 w0 = *reinterpret_cast<const float4*>(bp);
        b_pref[0]=w0.x; b_pref[1]=w0.y; b_pref[2]=w0.z; b_pref[3]=w0.w;
        if (BLD == 8) {
            const float4 w1 = *reinterpret_cast<const float4*>(bp + 4);
            b_pref[4]=w1.x; b_pref[5]=w1.y; b_pref[6]=w1.z; b_pref[7]=w1.w;
        }
    }
#pragma unroll
    for (int q = 0; q < 8; q++)   As[0][ar][ac + q] = f2tf32(a_pref[q]);
#pragma unroll
    for (int q = 0; q < BLD; q++) Bs[0][br][bc + q] = f2tf32(b_pref[q]);
    __syncthreads();

    const int nIter = K >> 4;
    for (int it = 0; it < nIter; it++) {
        const int cur = it & 1;
        const bool more = (it + 1 < nIter);
        if (more) {
            const int k0 = (it + 1) * 16;
            const float* ap;
            if (AMODE == 0) ap = A + (long long)(bm + ar) * lda + k0 + ac;
            else { const int tt = k0 + ac;
                   ap = A + (long long)(bm + ar) * 4096 + cellx * 512 + ((tt >> 3) << 6) + celly * 8; }
            const float4 v0 = *reinterpret_cast<const float4*>(ap);
            const float4 v1 = *reinterpret_cast<const float4*>(ap + 4);
            a_pref[0]=v0.x; a_pref[1]=v0.y; a_pref[2]=v0.z; a_pref[3]=v0.w;
            a_pref[4]=v1.x; a_pref[5]=v1.y; a_pref[6]=v1.z; a_pref[7]=v1.w;
            const float* bp = Bw + (long long)(bn + br) * ldb + k0 + bc;
            const float4 w0 = *reinterpret_cast<const float4*>(bp);
            b_pref[0]=w0.x; b_pref[1]=w0.y; b_pref[2]=w0.z; b_pref[3]=w0.w;
            if (BLD == 8) {
                const float4 w1 = *reinterpret_cast<const float4*>(bp + 4);
                b_pref[4]=w1.x; b_pref[5]=w1.y; b_pref[6]=w1.z; b_pref[7]=w1.w;
            }
        }
#pragma unroll
        for (int kk = 0; kk < 16; kk += 8) {
            uint32_t af[MF][4], bf[NF][2];
#pragma unroll
            for (int i = 0; i < MF; i++) {
                const int m = wm * WMS + i * 16;
                af[i][0] = As[cur][m + g][kk + t];
                af[i][1] = As[cur][m + 8 + g][kk + t];
                af[i][2] = As[cur][m + g][kk + t + 4];
                af[i][3] = As[cur][m + 8 + g][kk + t + 4];
            }
#pragma unroll
            for (int j = 0; j < NF; j++) {
                const int n = wn * 32 + j * 8;
                bf[j][0] = Bs[cur][n + g][kk + t];
                bf[j][1] = Bs[cur][n + g][kk + t + 4];
            }
#pragma unroll
            for (int i = 0; i < MF; i++)
#pragma unroll
                for (int j = 0; j < NF; j++) mma_tf32(acc[i][j], af[i], bf[j]);
        }
        if (more) {
            const int nxt = cur ^ 1;
#pragma unroll
            for (int q = 0; q < 8; q++)   As[nxt][ar][ac + q] = f2tf32(a_pref[q]);
#pragma unroll
            for (int q = 0; q < BLD; q++) Bs[nxt][br][bc + q] = f2tf32(b_pref[q]);
            __syncthreads();
        }
    }

    // ---- epilogue: plain store (+ optional bias) ----
#pragma unroll
    for (int i = 0; i < MF; i++) {
        const int row0 = bm + wm * WMS + i * 16 + g;
#pragma unroll
        for (int j = 0; j < NF; j++) {
            const int col = bn + wn * 32 + j * 8 + 2 * t;
            float bz0 = 0.f, bz1 = 0.f;
            if (bias) { bz0 = __ldg(&bias[col]); bz1 = __ldg(&bias[col + 1]); }
            *reinterpret_cast<float2*>(&C[(long long)row0 * N + col]) =
                make_float2(acc[i][j][0] + bz0, acc[i][j][1] + bz1);
            *reinterpret_cast<float2*>(&C[(long long)(row0 + 8) * N + col]) =
                make_float2(acc[i][j][2] + bz0, acc[i][j][3] + bz1);
        }
    }
}

// ---------------------------------------------------------------------------
// x1 = sum of 4 split-K partials + bias (deterministic)
__global__ void reduce_x1_kernel(const float* __restrict__ P, const float* __restrict__ bias,
                                 float* __restrict__ x1, int n4)
{
    const int idx = blockIdx.x * blockDim.x + threadIdx.x;   // over B*256/4
    if (idx >= n4) return;
    const float4 p0 = *reinterpret_cast<const float4*>(P + (size_t)0 * BSZ * 256 + idx * 4);
    const float4 p1 = *reinterpret_cast<const float4*>(P + (size_t)1 * BSZ * 256 + idx * 4);
    const float4 p2 = *reinterpret_cast<const float4*>(P + (size_t)2 * BSZ * 256 + idx * 4);
    const float4 p3 = *reinterpret_cast<const float4*>(P + (size_t)3 * BSZ * 256 + idx * 4);
    const int j0 = (idx * 4) & 255;
    const float4 b = *reinterpret_cast<const float4*>(bias + j0);
    float4 r;
    r.x = p0.x + p1.x + p2.x + p3.x + b.x;
    r.y = p0.y + p1.y + p2.y + p3.y + b.y;
    r.z = p0.z + p1.z + p2.z + p3.z + b.z;
    r.w = p0.w + p1.w + p2.w + p3.w + b.w;
    *reinterpret_cast<float4*>(x1 + idx * 4) = r;
}

// ---------------------------------------------------------------------------
__device__ __forceinline__ float sigf(float x) { return 1.f / (1.f + __expf(-x)); }
__device__ __forceinline__ float gru1f(float ir, float iz, float in,
                                       float hr, float hz, float hn, float h)
{
    const float r = sigf(ir + hr);
    const float z = sigf(iz + hz);
    const float n = tanhf(in + r * hn);
    return (1.f - z) * n + z * h;
}

__global__ void gru_elem_kernel(const float* __restrict__ gi, const float* __restrict__ gh,
                                const float* __restrict__ h0, float* __restrict__ hout,
                                int n4, long long giZ, long long hoZ)
{
    const long long z = blockIdx.z;
    const int idx = blockIdx.x * blockDim.x + threadIdx.x;   // over B*64
    if (idx >= n4) return;
    const int b = idx >> 6;
    const int j = (idx & 63) * 4;
    const float* g  = gi + z * giZ + (long long)b * 768;
    const float* q  = gh + (long long)b * 768;
    const float4 ir = *reinterpret_cast<const float4*>(g + j);
    const float4 iz = *reinterpret_cast<const float4*>(g + 256 + j);
    const float4 in = *reinterpret_cast<const float4*>(g + 512 + j);
    const float4 hr = *reinterpret_cast<const float4*>(q + j);
    const float4 hz = *reinterpret_cast<const float4*>(q + 256 + j);
    const float4 hn = *reinterpret_cast<const float4*>(q + 512 + j);
    const float4 hh = *reinterpret_cast<const float4*>(h0 + (long long)b * 256 + j);
    float4 r;
    r.x = gru1f(ir.x, iz.x, in.x, hr.x, hz.x, hn.x, hh.x);
    r.y = gru1f(ir.y, iz.y, in.y, hr.y, hz.y, hn.y, hh.y);
    r.z = gru1f(ir.z, iz.z, in.z, hr.z, hz.z, hn.z, hh.z);
    r.w = gru1f(ir.w, iz.w, in.w, hr.w, hz.w, hn.w, hh.w);
    *reinterpret_cast<float4*>(hout + z * hoZ + (long long)b * 256 + j) = r;
}

// ---------------------------------------------------------------------------
// y[b,i,j] = o1[b,i] + (cmap[cell(i,j)]>=0 ? o2[k,b,(i&7)*8+(j&7)] : 0)
__global__ void assemble_y_kernel(const float* __restrict__ o1, const float* __restrict__ o2,
                                  const int* __restrict__ cmap, float* __restrict__ y, int n4)
{
    const int idx = blockIdx.x * blockDim.x + threadIdx.x;   // over B*1024
    if (idx >= n4) return;
    const int b   = idx >> 10;
    const int rem = idx & 1023;
    const int i   = rem >> 4;            // 0..63
    const int j0  = (rem & 15) * 4;      // 0..60
    const float v = __ldg(&o1[b * 64 + i]);
    float4 r = make_float4(v, v, v, v);
    const int k = cmap[(i >> 3) * 8 + (j0 >> 3)];
    if (k >= 0) {
        const int t = (i & 7) * 8 + (j0 & 7);
        const float4 a = *reinterpret_cast<const float4*>(o2 + ((long long)k * BSZ + b) * 64 + t);
        r.x += a.x; r.y += a.y; r.z += a.z; r.w += a.w;
    }
    *reinterpret_cast<float4*>(y + (long long)idx * 4) = r;
}

// ---------------------------------------------------------------------------
extern "C" void kernel_launch(void* const* d_in, const int* in_sizes, int n_in,
                              void* d_out, int out_size)
{
    const float* x    = (const float*)d_in[0];
    const float* h    = (const float*)d_in[1];
    const float* fa   = (const float*)d_in[2];
    const float* e1w  = (const float*)d_in[3];
    const float* e1b  = (const float*)d_in[4];
    const float* wih1 = (const float*)d_in[5];
    const float* whh1 = (const float*)d_in[6];
    const float* bih1 = (const float*)d_in[7];
    const float* bhh1 = (const float*)d_in[8];
    const float* o1w  = (const float*)d_in[9];
    const float* o1b  = (const float*)d_in[10];
    const float* e2w  = (const float*)d_in[11];
    const float* e2b  = (const float*)d_in[12];
    const float* wih2 = (const float*)d_in[13];
    const float* whh2 = (const float*)d_in[14];
    const float* bih2 = (const float*)d_in[15];
    const float* bhh2 = (const float*)d_in[16];
    const float* o2w  = (const float*)d_in[17];
    const float* o2b  = (const float*)d_in[18];
    float* out = (float*)d_out;

    const int B = in_sizes[0] / 4096;                  // 2048
    const long long YOFF = (long long)B * 4096;
    int Kc = (int)(((long long)out_size - YOFF) / ((long long)B * 256)) - 1;
    if (Kc < 0) Kc = 0;
    if (Kc > MAXK) Kc = MAXK;

    float *p_xp, *p_x1, *p_gi1, *p_gh1, *p_gh2, *p_gi2, *p_o1, *p_o2, *p_w2p, *p_b2p;
    int *p_cx, *p_cy, *p_cmap;
    cudaGetSymbolAddress((void**)&p_xp,   d_xp);
    cudaGetSymbolAddress((void**)&p_x1,   d_x1);
    cudaGetSymbolAddress((void**)&p_gi1,  d_gi1);
    cudaGetSymbolAddress((void**)&p_gh1,  d_gh1);
    cudaGetSymbolAddress((void**)&p_gh2,  d_gh2);
    cudaGetSymbolAddress((void**)&p_gi2,  d_gi2);
    cudaGetSymbolAddress((void**)&p_o1,   d_o1);
    cudaGetSymbolAddress((void**)&p_o2,   d_o2);
    cudaGetSymbolAddress((void**)&p_w2p,  d_w2p);
    cudaGetSymbolAddress((void**)&p_b2p,  d_b2p);
    cudaGetSymbolAddress((void**)&p_cx,   d_cx);
    cudaGetSymbolAddress((void**)&p_cy,   d_cy);
    cudaGetSymbolAddress((void**)&p_cmap, d_cmap);

    float* yh0 = out + YOFF;                           // h1 slot
    float* yh2 = out + YOFF + (long long)B * 256;      // h2 slots

    find_cells_kernel<<<1, 32>>>(fa, p_cx, p_cy, p_cmap);
    compose_w2_kernel<<<768, 64>>>(wih2, e2w, e2b, bih2, p_w2p, p_b2p);

    // x1 split-K=4 partials: (N=256, K slab=1024)
    gemm_tc<128, 0><<<dim3(2, B / 128, 4), 256>>>(x, e1w, nullptr, p_xp,
                                                  B, 256, 1024, 4096, 4096,
                                                  1024, 1024, (long long)B * 256,
                                                  nullptr, nullptr);
    reduce_x1_kernel<<<(B * 64 + 255) / 256, 256>>>(p_xp, e1b, p_x1, B * 64);

    // gh1, gh2 (N=768, K=256)
    gemm_tc<128, 0><<<dim3(6, B / 128), 256>>>(h, whh1, bhh1, p_gh1,
                                               B, 768, 256, 256, 256, 0, 0, 0, nullptr, nullptr);
    gemm_tc<128, 0><<<dim3(6, B / 128), 256>>>(h, whh2, bhh2, p_gh2,
                                               B, 768, 256, 256, 256, 0, 0, 0, nullptr, nullptr);
    // gi1 = x1 @ wih1^T + b
    gemm_tc<128, 0><<<dim3(6, B / 128), 256>>>(p_x1, wih1, bih1, p_gi1,
                                               B, 768, 256, 256, 256, 0, 0, 0, nullptr, nullptr);
    // h1 -> out y_h[0]
    gru_elem_kernel<<<dim3((B * 64 + 255) / 256, 1, 1), 256>>>(p_gi1, p_gh1, h, yh0,
                                                               B * 64, 0, 0);
    // o1 = h1 @ o1w^T + b  (N=64, K=256)
    gemm_tc<64, 0><<<dim3(1, B / 128), 256>>>(yh0, o1w, o1b, p_o1,
                                              B, 64, 256, 256, 256, 0, 0, 0, nullptr, nullptr);

    if (Kc > 0) {
        // gi2[k] = patch[k] @ W2p^T + b2p  (gather A; N=768, K=64)
        gemm_tc<128, 1><<<dim3(6, B / 128, Kc), 256>>>(x, p_w2p, p_b2p, p_gi2,
                                                       B, 768, 64, 64, 64,
                                                       0, 0, (long long)B * 768, p_cx, p_cy);
        // h2[k] -> out y_h[1+k]
        gru_elem_kernel<<<dim3((B * 64 + 255) / 256, 1, Kc), 256>>>(p_gi2, p_gh2, h, yh2,
                                                                    B * 64,
                                                                    (long long)B * 768,
                                                                    (long long)B * 256);
        // o2[k] = h2[k] @ o2w^T + b  (N=64, K=256)
        gemm_tc<64, 0><<<dim3(1, B / 128, Kc), 256>>>(yh2, o2w, o2b, p_o2,
                                                      B, 64, 256, 256, 256,
                                                      (long long)B * 256, 0, (long long)B * 64,
                                                      nullptr, nullptr);
    }
    // y = bcast(o1) + scatter(o2)
    assemble_y_kernel<<<(B * 1024 + 255) / 256, 256>>>(p_o1, p_o2, p_cmap, out, B * 1024);
}